// round 15
// baseline (speedup 1.0000x reference)
#include <cuda_runtime.h>
#include <cuda_fp16.h>
#include <cstdint>

#define N_R   100000
#define N_E   1200000
#define G_N   4096
#define H     64
#define ED    16
#define LYR   4
#define FNB   64
#define FEMAX 512

// ---------------- scratch (device globals; allocation-free) ----------------
__device__ float   g_h[(size_t)N_R * H];
__device__ __half2 g_h16a[(size_t)N_R * (H / 2)];
__device__ __half2 g_h16b[(size_t)N_R * (H / 2)];
__device__ float   g_hsa[N_R];
__device__ float   g_hda[N_R];
__device__ float   g_hsb[N_R];
__device__ float   g_hdb[N_R];
__device__ uint4   g_recsr[(size_t)N_E * 2];
__device__ int     g_deg[N_R];
__device__ int     g_off[N_R + 1];
__device__ int     g_cur[N_R];
__device__ int     g_srcs[N_E];
__device__ int     g_perm[N_E];
__device__ int     g_gcnt[G_N];
__device__ int     g_goff[G_N + 1];
__device__ int     g_bsums[256];

__device__ __forceinline__ unsigned pack_half2(float a, float b) {
    __half2 h = __floats2half2_rn(a, b);
    return *reinterpret_cast<unsigned*>(&h);
}

// ---------------- fused setup kernels ----------------
__global__ void zero_fused(int* deg, int* cur, int* gcnt, int nN, int nG) {
    int i = blockIdx.x * blockDim.x + threadIdx.x;
    if (i < nN) { deg[i] = 0; cur[i] = 0; }
    if (i < nG) gcnt[i] = 0;
}
__global__ void hist_fused(const int* __restrict__ dst, const int* __restrict__ gid,
                           int* __restrict__ deg, int* __restrict__ gcnt,
                           int nE, int nN) {
    int i = blockIdx.x * blockDim.x + threadIdx.x;
    if (i < nE) atomicAdd(&deg[dst[i]], 1);
    if (i < nN) atomicAdd(&gcnt[gid[i]], 1);
}

// ---- multi-block exclusive scan ----
__global__ void scan_block(const int* __restrict__ cnt, int* __restrict__ off,
                           int* __restrict__ sums, int n) {
    __shared__ int wsum[32];
    int tid = threadIdx.x;
    int i = blockIdx.x * 1024 + tid;
    int v = (i < n) ? cnt[i] : 0;
    int x = v;
    #pragma unroll
    for (int d = 1; d < 32; d <<= 1) {
        int y = __shfl_up_sync(0xffffffffu, x, d);
        if ((tid & 31) >= d) x += y;
    }
    if ((tid & 31) == 31) wsum[tid >> 5] = x;
    __syncthreads();
    if (tid < 32) {
        int w = wsum[tid];
        #pragma unroll
        for (int d = 1; d < 32; d <<= 1) {
            int y = __shfl_up_sync(0xffffffffu, w, d);
            if (tid >= d) w += y;
        }
        wsum[tid] = w;
    }
    __syncthreads();
    int incl = x + ((tid >= 32) ? wsum[(tid >> 5) - 1] : 0);
    if (i < n) off[i + 1] = incl;
    if (tid == 1023) sums[blockIdx.x] = incl;
}
__global__ void scan_sums_par(int* sums, int nb) {
    __shared__ int ws[4];
    int tid = threadIdx.x;
    int lane = tid & 31;
    int v = (tid < nb) ? sums[tid] : 0;
    int x = v;
    #pragma unroll
    for (int d = 1; d < 32; d <<= 1) {
        int y = __shfl_up_sync(0xffffffffu, x, d);
        if (lane >= d) x += y;
    }
    if (lane == 31) ws[tid >> 5] = x;
    __syncthreads();
    if (tid == 0) {
        int a = 0;
        #pragma unroll
        for (int j = 0; j < 4; j++) { int t = ws[j]; ws[j] = a; a += t; }
    }
    __syncthreads();
    x += ws[tid >> 5];
    if (tid < nb) sums[tid] = x - v;
}
__global__ void add_base(int* __restrict__ off, const int* __restrict__ sums, int n) {
    int i = blockIdx.x * 1024 + threadIdx.x;
    if (i == 0) off[0] = 0;
    if (i < n) off[i + 1] += sums[blockIdx.x];
}

__global__ void scatter_kernel(const int* __restrict__ src, const int* __restrict__ dst,
                               const int* __restrict__ off, int* __restrict__ cur,
                               int* __restrict__ perm, int* __restrict__ srcs, int n) {
    int e = blockIdx.x * blockDim.x + threadIdx.x;
    if (e < n) {
        int d = dst[e];
        int p = off[d] + atomicAdd(&cur[d], 1);
        perm[p] = e;
        srcs[p] = src[e];
    }
}

// ---------------- tensor-core node GEMM (R13-proven; embed only) ------------
__global__ void __launch_bounds__(256)
gemm64_kernel(const float* __restrict__ in, const float* __restrict__ W,
              const float* __restrict__ resid, float* __restrict__ out,
              __half2* __restrict__ out16,
              const float* __restrict__ as_, const float* __restrict__ ad_,
              float* __restrict__ hs, float* __restrict__ hd,
              int n, int do_lrelu) {
    __shared__ float  sW[64 * 64];
    __shared__ __half sA[64][72];
    __shared__ float  sRed[64][4];
    int tid = threadIdx.x;
    int lane = tid & 31;
    int w = tid >> 5;
    int wr = (w & 3) * 16;
    int cg = w >> 2;

    for (int i = tid; i < 4096; i += 256) sW[i] = W[i];
    __syncthreads();
    unsigned bfr[4][4][2];
    {
        int col = cg * 32 + (lane >> 2);
        int k0 = (lane & 3) * 2;
        #pragma unroll
        for (int f = 0; f < 4; f++) {
            int c = col + f * 8;
            #pragma unroll
            for (int s = 0; s < 4; s++) {
                int kk = s * 16 + k0;
                bfr[f][s][0] = pack_half2(sW[kk * 64 + c],       sW[(kk + 1) * 64 + c]);
                bfr[f][s][1] = pack_half2(sW[(kk + 8) * 64 + c], sW[(kk + 9) * 64 + c]);
            }
        }
    }

    float as0[8], ad0[8];
    if (as_) {
        #pragma unroll
        for (int f = 0; f < 4; f++) {
            int c = cg * 32 + f * 8 + 2 * (lane & 3);
            as0[2 * f]     = as_[c];     as0[2 * f + 1] = as_[c + 1];
            ad0[2 * f]     = ad_[c];     ad0[2 * f + 1] = ad_[c + 1];
        }
    }

    int ntiles = (n + 63) / 64;
    for (int t = blockIdx.x; t < ntiles; t += gridDim.x) {
        int base = t * 64;
        __syncthreads();
        for (int i = tid; i < 2048; i += 256) {
            int row = i >> 5;
            int k0 = (i & 31) * 2;
            int node = base + row;
            float2 v = (node < n) ? *(const float2*)(in + (size_t)node * H + k0)
                                  : make_float2(0.f, 0.f);
            *(__half2*)&sA[row][k0] = __floats2half2_rn(v.x, v.y);
        }
        __syncthreads();

        float c[4][4];
        #pragma unroll
        for (int f = 0; f < 4; f++)
            #pragma unroll
            for (int j = 0; j < 4; j++) c[f][j] = 0.f;

        int r = lane >> 2, k0 = (lane & 3) * 2;
        #pragma unroll
        for (int s = 0; s < 4; s++) {
            unsigned a0 = *(unsigned*)&sA[wr + r][s * 16 + k0];
            unsigned a1 = *(unsigned*)&sA[wr + r + 8][s * 16 + k0];
            unsigned a2 = *(unsigned*)&sA[wr + r][s * 16 + 8 + k0];
            unsigned a3 = *(unsigned*)&sA[wr + r + 8][s * 16 + 8 + k0];
            #pragma unroll
            for (int f = 0; f < 4; f++) {
                asm volatile(
                    "mma.sync.aligned.m16n8k16.row.col.f32.f16.f16.f32 "
                    "{%0,%1,%2,%3}, {%4,%5,%6,%7}, {%8,%9}, {%0,%1,%2,%3};"
                    : "+f"(c[f][0]), "+f"(c[f][1]), "+f"(c[f][2]), "+f"(c[f][3])
                    : "r"(a0), "r"(a1), "r"(a2), "r"(a3),
                      "r"(bfr[f][s][0]), "r"(bfr[f][s][1]));
            }
        }

        int rowA = wr + (lane >> 2);
        int rowB = rowA + 8;
        int nodeA = base + rowA;
        int nodeB = base + rowB;
        float psA = 0.f, pdA = 0.f, psB = 0.f, pdB = 0.f;
        #pragma unroll
        for (int f = 0; f < 4; f++) {
            int col = cg * 32 + f * 8 + 2 * (lane & 3);
            float v0 = c[f][0], v1 = c[f][1];
            float u0 = c[f][2], u1 = c[f][3];
            if (resid) {
                if (nodeA < n) {
                    float2 rr = *(const float2*)(resid + (size_t)nodeA * H + col);
                    v0 += rr.x; v1 += rr.y;
                }
                if (nodeB < n) {
                    float2 rr = *(const float2*)(resid + (size_t)nodeB * H + col);
                    u0 += rr.x; u1 += rr.y;
                }
            }
            if (do_lrelu) {
                v0 = v0 > 0.f ? v0 : 0.1f * v0;  v1 = v1 > 0.f ? v1 : 0.1f * v1;
                u0 = u0 > 0.f ? u0 : 0.1f * u0;  u1 = u1 > 0.f ? u1 : 0.1f * u1;
            }
            if (nodeA < n) {
                *(float2*)(out + (size_t)nodeA * H + col) = make_float2(v0, v1);
                out16[(size_t)nodeA * 32 + (col >> 1)] = __floats2half2_rn(v0, v1);
            }
            if (nodeB < n) {
                *(float2*)(out + (size_t)nodeB * H + col) = make_float2(u0, u1);
                out16[(size_t)nodeB * 32 + (col >> 1)] = __floats2half2_rn(u0, u1);
            }
            if (as_) {
                psA += v0 * as0[2 * f] + v1 * as0[2 * f + 1];
                pdA += v0 * ad0[2 * f] + v1 * ad0[2 * f + 1];
                psB += u0 * as0[2 * f] + u1 * as0[2 * f + 1];
                pdB += u0 * ad0[2 * f] + u1 * ad0[2 * f + 1];
            }
        }
        if (as_) {
            #pragma unroll
            for (int d = 1; d < 4; d <<= 1) {
                psA += __shfl_xor_sync(0xffffffffu, psA, d);
                pdA += __shfl_xor_sync(0xffffffffu, pdA, d);
                psB += __shfl_xor_sync(0xffffffffu, psB, d);
                pdB += __shfl_xor_sync(0xffffffffu, pdB, d);
            }
            if ((lane & 3) == 0) {
                sRed[rowA][cg * 2 + 0] = psA;  sRed[rowA][cg * 2 + 1] = pdA;
                sRed[rowB][cg * 2 + 0] = psB;  sRed[rowB][cg * 2 + 1] = pdB;
            }
            __syncthreads();
            if (tid < 64 && base + tid < n) {
                hs[base + tid] = sRed[tid][0] + sRed[tid][2];
                hd[base + tid] = sRed[tid][1] + sRed[tid][3];
            }
        }
    }
}

// ---------------- build recsr ----------------
__global__ void __launch_bounds__(256)
build_recsr_kernel(const float* __restrict__ r_edge, const int* __restrict__ perm,
                   uint4* __restrict__ recsr, int n_e) {
    int p = blockIdx.x * blockDim.x + threadIdx.x;
    if (p >= n_e) return;
    int eid = __ldg(&perm[p]);
    const float4* rp = (const float4*)(r_edge + (size_t)eid * ED);
    float4 q0 = rp[0], q1 = rp[1], q2 = rp[2], q3 = rp[3];
    __half2 hv[8];
    hv[0] = __floats2half2_rn(q0.x, q0.y);
    hv[1] = __floats2half2_rn(q0.z, q0.w);
    hv[2] = __floats2half2_rn(q1.x, q1.y);
    hv[3] = __floats2half2_rn(q1.z, q1.w);
    hv[4] = __floats2half2_rn(q2.x, q2.y);
    hv[5] = __floats2half2_rn(q2.z, q2.w);
    hv[6] = __floats2half2_rn(q3.x, q3.y);
    hv[7] = __floats2half2_rn(q3.z, q3.w);
    recsr[(size_t)p * 2]     = *(uint4*)&hv[0];
    recsr[(size_t)p * 2 + 1] = *(uint4*)&hv[4];
}

// ---------------- FUSED attention layer + Wm GEMM (64 nodes per block) -------
// Phase A: edge-parallel exp-logits; Phase 2: warp-per-8-nodes weighted gather
// + 16-dim edge aggregation; agg tile -> smem fp16; MMA with Wm; epilogue:
// resid (fp32 h, own nodes), lrelu, write h + h16_out, hs/hd dots for next layer.
__global__ void __launch_bounds__(256)
fused_layer_kernel(const int* __restrict__ off, const int* __restrict__ srcs,
                   const uint4* __restrict__ recsr,
                   const float* __restrict__ W_e, const float* __restrict__ a_e, int l,
                   const float* __restrict__ Wm,
                   const float* __restrict__ hs_in, const float* __restrict__ hd_in,
                   const __half2* __restrict__ h16_in,
                   float* __restrict__ h, __half2* __restrict__ h16_out,
                   const float* __restrict__ as_, const float* __restrict__ ad_,
                   float* __restrict__ hs_out, float* __restrict__ hd_out,
                   int n) {
    __shared__ float  sWe[ED * H];       // 4 KB
    __shared__ float  sw16[ED];
    __shared__ int    s_off[FNB + 1];
    __shared__ float  s_hdv[FNB];
    __shared__ float  s_sum[FNB];
    __shared__ float  s_w[FEMAX];        // 2 KB
    __shared__ int    s_src[FEMAX];      // 2 KB
    __shared__ uint4  s_re[FEMAX * 2];   // 16 KB
    __shared__ float  sW[4096];          // 16 KB (Wm)
    __shared__ __half sA[64][72];        // 9.2 KB (agg tile)
    __shared__ float  sRed[64][4];       // 1 KB
    int tid = threadIdx.x, lane = tid & 31, w = tid >> 5;
    int node0 = blockIdx.x * FNB;
    for (int i = tid; i < ED * H; i += 256) sWe[i] = W_e[i];
    for (int i = tid; i < 4096; i += 256) sW[i] = Wm[i];
    if (tid <= FNB) {
        int nd = node0 + tid;
        s_off[tid] = off[nd <= n ? nd : n];
    }
    if (tid < FNB) {
        s_sum[tid] = 0.f;
        int nd = node0 + tid;
        s_hdv[tid] = (nd < n) ? hd_in[nd] : 0.f;
    }
    __syncthreads();
    if (tid < ED) {
        float s = 0.f;
        const float* ae = a_e + l * H;
        #pragma unroll 8
        for (int j = 0; j < H; j++) s += sWe[tid * H + j] * ae[j];
        sw16[tid] = s;
    }
    __syncthreads();

    int base = s_off[0], endall = s_off[FNB];
    float acc[8][2];
    float acc16[8];
    #pragma unroll
    for (int j = 0; j < 8; j++) { acc[j][0] = 0.f; acc[j][1] = 0.f; acc16[j] = 0.f; }

    for (int cs = base; cs < endall; cs += FEMAX) {
        int cnt = min(FEMAX, endall - cs);
        // phase A: edge-parallel exp(logit)
        for (int i = tid; i < cnt; i += 256) {
            int p = cs + i;
            int sv = __ldg(&srcs[p]);
            uint4 ra = __ldg(&recsr[(size_t)p * 2]);
            uint4 rb = __ldg(&recsr[(size_t)p * 2 + 1]);
            const __half2* ha = (const __half2*)&ra;
            const __half2* hb = (const __half2*)&rb;
            float ea = 0.f;
            #pragma unroll
            for (int j = 0; j < 4; j++) {
                float2 f = __half22float2(ha[j]);
                ea += f.x * sw16[2 * j] + f.y * sw16[2 * j + 1];
            }
            #pragma unroll
            for (int j = 0; j < 4; j++) {
                float2 f = __half22float2(hb[j]);
                ea += f.x * sw16[8 + 2 * j] + f.y * sw16[8 + 2 * j + 1];
            }
            int lo = 0, hi = FNB;
            #pragma unroll
            for (int b = 0; b < 6; b++) {
                int mid = (lo + hi) >> 1;
                bool ge = (p >= s_off[mid]);
                lo = ge ? mid : lo;
                hi = ge ? hi : mid;
            }
            float lg = __ldg(&hs_in[sv]) + s_hdv[lo] + ea;
            lg = lg > 0.f ? lg : 0.1f * lg;
            float ew = __expf(fminf(lg, 85.f));
            s_w[i] = ew;
            s_src[i] = sv;
            s_re[i * 2]     = ra;
            s_re[i * 2 + 1] = rb;
            atomicAdd(&s_sum[lo], ew);
        }
        __syncthreads();
        // phase 2: warp per 8 nodes
        const __half* s_reh = (const __half*)s_re;
        #pragma unroll
        for (int j = 0; j < 8; j++) {
            int ndl = w * 8 + j;
            int lo = max(s_off[ndl], cs) - cs;
            int hi = min(s_off[ndl + 1], cs + cnt) - cs;
            #pragma unroll 4
            for (int i = lo; i < hi; i++) {
                float wv = s_w[i];
                int sv = s_src[i];
                float2 hp = __half22float2(h16_in[(size_t)sv * 32 + lane]);
                acc[j][0] += wv * hp.x;
                acc[j][1] += wv * hp.y;
                if (lane < ED)
                    acc16[j] += wv * __half2float(s_reh[i * ED + lane]);
            }
        }
        __syncthreads();
    }
    // agg epilogue -> sA (fp16)
    #pragma unroll
    for (int j = 0; j < 8; j++) {
        int ndl = w * 8 + j;
        float a0 = acc[j][0], a1 = acc[j][1];
        #pragma unroll
        for (int k = 0; k < ED; k++) {
            float b = __shfl_sync(0xffffffffu, acc16[j], k);
            a0 += b * sWe[k * H + 2 * lane];
            a1 += b * sWe[k * H + 2 * lane + 1];
        }
        float s = s_sum[ndl];
        float inv = (s > 0.f) ? (1.0f / s) : 0.f;
        *(__half2*)&sA[ndl][2 * lane] = __floats2half2_rn(a0 * inv, a1 * inv);
    }
    __syncthreads();

    // ---- GEMM phase (gemm64 tile code, single tile) ----
    int wr = (w & 3) * 16, cg = w >> 2;
    unsigned bfr[4][4][2];
    {
        int col = cg * 32 + (lane >> 2);
        int k0 = (lane & 3) * 2;
        #pragma unroll
        for (int f = 0; f < 4; f++) {
            int c = col + f * 8;
            #pragma unroll
            for (int s = 0; s < 4; s++) {
                int kk = s * 16 + k0;
                bfr[f][s][0] = pack_half2(sW[kk * 64 + c],       sW[(kk + 1) * 64 + c]);
                bfr[f][s][1] = pack_half2(sW[(kk + 8) * 64 + c], sW[(kk + 9) * 64 + c]);
            }
        }
    }
    float c4[4][4];
    #pragma unroll
    for (int f = 0; f < 4; f++)
        #pragma unroll
        for (int j = 0; j < 4; j++) c4[f][j] = 0.f;
    {
        int r = lane >> 2, k0 = (lane & 3) * 2;
        #pragma unroll
        for (int s = 0; s < 4; s++) {
            unsigned a0 = *(unsigned*)&sA[wr + r][s * 16 + k0];
            unsigned a1 = *(unsigned*)&sA[wr + r + 8][s * 16 + k0];
            unsigned a2 = *(unsigned*)&sA[wr + r][s * 16 + 8 + k0];
            unsigned a3 = *(unsigned*)&sA[wr + r + 8][s * 16 + 8 + k0];
            #pragma unroll
            for (int f = 0; f < 4; f++) {
                asm volatile(
                    "mma.sync.aligned.m16n8k16.row.col.f32.f16.f16.f32 "
                    "{%0,%1,%2,%3}, {%4,%5,%6,%7}, {%8,%9}, {%0,%1,%2,%3};"
                    : "+f"(c4[f][0]), "+f"(c4[f][1]), "+f"(c4[f][2]), "+f"(c4[f][3])
                    : "r"(a0), "r"(a1), "r"(a2), "r"(a3),
                      "r"(bfr[f][s][0]), "r"(bfr[f][s][1]));
            }
        }
    }
    // epilogue: resid + lrelu + writes + next-layer dots
    float as0[8], ad0[8];
    if (as_) {
        #pragma unroll
        for (int f = 0; f < 4; f++) {
            int c = cg * 32 + f * 8 + 2 * (lane & 3);
            as0[2 * f]     = as_[c];     as0[2 * f + 1] = as_[c + 1];
            ad0[2 * f]     = ad_[c];     ad0[2 * f + 1] = ad_[c + 1];
        }
    }
    int rowA = wr + (lane >> 2);
    int rowB = rowA + 8;
    int nodeA = node0 + rowA;
    int nodeB = node0 + rowB;
    float psA = 0.f, pdA = 0.f, psB = 0.f, pdB = 0.f;
    #pragma unroll
    for (int f = 0; f < 4; f++) {
        int col = cg * 32 + f * 8 + 2 * (lane & 3);
        float v0 = c4[f][0], v1 = c4[f][1];
        float u0 = c4[f][2], u1 = c4[f][3];
        if (nodeA < n) {
            float2 rr = *(const float2*)(h + (size_t)nodeA * H + col);
            v0 += rr.x; v1 += rr.y;
        }
        if (nodeB < n) {
            float2 rr = *(const float2*)(h + (size_t)nodeB * H + col);
            u0 += rr.x; u1 += rr.y;
        }
        v0 = v0 > 0.f ? v0 : 0.1f * v0;  v1 = v1 > 0.f ? v1 : 0.1f * v1;
        u0 = u0 > 0.f ? u0 : 0.1f * u0;  u1 = u1 > 0.f ? u1 : 0.1f * u1;
        if (nodeA < n) {
            *(float2*)(h + (size_t)nodeA * H + col) = make_float2(v0, v1);
            h16_out[(size_t)nodeA * 32 + (col >> 1)] = __floats2half2_rn(v0, v1);
        }
        if (nodeB < n) {
            *(float2*)(h + (size_t)nodeB * H + col) = make_float2(u0, u1);
            h16_out[(size_t)nodeB * 32 + (col >> 1)] = __floats2half2_rn(u0, u1);
        }
        if (as_) {
            psA += v0 * as0[2 * f] + v1 * as0[2 * f + 1];
            pdA += v0 * ad0[2 * f] + v1 * ad0[2 * f + 1];
            psB += u0 * as0[2 * f] + u1 * as0[2 * f + 1];
            pdB += u0 * ad0[2 * f] + u1 * ad0[2 * f + 1];
        }
    }
    if (as_) {
        #pragma unroll
        for (int d = 1; d < 4; d <<= 1) {
            psA += __shfl_xor_sync(0xffffffffu, psA, d);
            pdA += __shfl_xor_sync(0xffffffffu, pdA, d);
            psB += __shfl_xor_sync(0xffffffffu, psB, d);
            pdB += __shfl_xor_sync(0xffffffffu, pdB, d);
        }
        if ((lane & 3) == 0) {
            sRed[rowA][cg * 2 + 0] = psA;  sRed[rowA][cg * 2 + 1] = pdA;
            sRed[rowB][cg * 2 + 0] = psB;  sRed[rowB][cg * 2 + 1] = pdB;
        }
        __syncthreads();
        if (tid < 64 && node0 + tid < n) {
            hs_out[node0 + tid] = sRed[tid][0] + sRed[tid][2];
            hd_out[node0 + tid] = sRed[tid][1] + sRed[tid][3];
        }
    }
}

// ---------------- fused pool + interaction + MLP readout (h16 input) --------
__global__ void __launch_bounds__(256)
poolmlp_kernel(const int* __restrict__ goff, const float* __restrict__ d_edge,
               const float* __restrict__ w_d, const float* __restrict__ b_d,
               const float* __restrict__ i_node, const float* __restrict__ W_i,
               const __half2* __restrict__ h16,
               const float* __restrict__ W_mlp, const float* __restrict__ b_mlp,
               const float* __restrict__ W_out, const float* __restrict__ b_out,
               float* __restrict__ out, int g_total) {
    __shared__ float sW[3 * 4096];
    __shared__ float sb[3 * 64];
    __shared__ float sWo[64];
    __shared__ float sx[8][64];
    int tid = threadIdx.x, lane = tid & 31, wl = tid >> 5;
    for (int i = tid; i < 3 * 4096; i += 256) sW[i] = W_mlp[i];
    if (tid < 192) sb[tid] = b_mlp[tid];
    if (tid < 64) sWo[tid] = W_out[tid];
    __syncthreads();
    float wd = w_d[0], bd = b_d[0], bo = b_out[0];
    int g = blockIdx.x * 8 + wl;
    if (g >= g_total) return;

    int beg = goff[g], end = goff[g + 1];
    float s00 = 0.f, s01 = 0.f, s10 = 0.f, s11 = 0.f, sg = 0.f;
    for (int nn = beg; nn < end; nn++) {
        float gate = 1.0f / (1.0f + __expf(-(d_edge[nn] * wd + bd)));
        float2 hp = __half22float2(h16[(size_t)nn * 32 + lane]);
        s00 += hp.x; s01 += hp.y;
        s10 += gate * hp.x; s11 += gate * hp.y;
        sg += gate;
    }
    float iv = i_node[g];
    float hi0 = iv * W_i[2 * lane] + s10;
    float hi1 = iv * W_i[2 * lane + 1] + s11;
    sx[wl][2 * lane]     = s00 + sg * hi0;
    sx[wl][2 * lane + 1] = s01 + sg * hi1;
    __syncwarp();

    for (int l = 0; l < 3; l++) {
        float a0 = sb[l * 64 + 2 * lane];
        float a1 = sb[l * 64 + 2 * lane + 1];
        const float* Wl = sW + l * 4096;
        #pragma unroll 8
        for (int k = 0; k < 64; k++) {
            float xv = sx[wl][k];
            a0 += xv * Wl[k * 64 + 2 * lane];
            a1 += xv * Wl[k * 64 + 2 * lane + 1];
        }
        a0 = fmaxf(a0, 0.f);
        a1 = fmaxf(a1, 0.f);
        __syncwarp();
        sx[wl][2 * lane]     = a0;
        sx[wl][2 * lane + 1] = a1;
        __syncwarp();
    }
    float part = sx[wl][2 * lane] * sWo[2 * lane] + sx[wl][2 * lane + 1] * sWo[2 * lane + 1];
    #pragma unroll
    for (int d = 16; d; d >>= 1) part += __shfl_xor_sync(0xffffffffu, part, d);
    if (lane == 0) out[g] = part + bo;
}

// ---------------- launcher ----------------
extern "C" void kernel_launch(void* const* d_in, const int* in_sizes, int n_in,
                              void* d_out, int out_size) {
    const float* r_node  = (const float*)d_in[0];
    const float* i_node  = (const float*)d_in[1];
    const float* r_edge  = (const float*)d_in[2];
    const float* d_edge  = (const float*)d_in[3];
    const int*   r2r_src = (const int*)d_in[4];
    const int*   r2r_dst = (const int*)d_in[5];
    const int*   graph_id= (const int*)d_in[6];
    const float* W_r     = (const float*)d_in[7];
    const float* W_i     = (const float*)d_in[8];
    const float* W_e     = (const float*)d_in[9];
    const float* Wm      = (const float*)d_in[10];
    const float* a_s     = (const float*)d_in[11];
    const float* a_d     = (const float*)d_in[12];
    const float* a_e     = (const float*)d_in[13];
    const float* w_d     = (const float*)d_in[14];
    const float* b_d     = (const float*)d_in[15];
    const float* W_mlp   = (const float*)d_in[16];
    const float* b_mlp   = (const float*)d_in[17];
    const float* W_out   = (const float*)d_in[18];
    const float* b_out   = (const float*)d_in[19];
    float* out = (float*)d_out;

    const int nN = in_sizes[3];
    const int nE = in_sizes[4];
    const int nG = in_sizes[1];

    float *p_h, *p_hsa, *p_hda, *p_hsb, *p_hdb;
    __half2 *p_h16a, *p_h16b;
    uint4*   p_recsr;
    int *p_deg, *p_off, *p_cur, *p_srcs, *p_perm, *p_gcnt, *p_goff, *p_bsums;
    cudaGetSymbolAddress((void**)&p_h, g_h);
    cudaGetSymbolAddress((void**)&p_h16a, g_h16a);
    cudaGetSymbolAddress((void**)&p_h16b, g_h16b);
    cudaGetSymbolAddress((void**)&p_hsa, g_hsa);
    cudaGetSymbolAddress((void**)&p_hda, g_hda);
    cudaGetSymbolAddress((void**)&p_hsb, g_hsb);
    cudaGetSymbolAddress((void**)&p_hdb, g_hdb);
    cudaGetSymbolAddress((void**)&p_recsr, g_recsr);
    cudaGetSymbolAddress((void**)&p_deg, g_deg);
    cudaGetSymbolAddress((void**)&p_off, g_off);
    cudaGetSymbolAddress((void**)&p_cur, g_cur);
    cudaGetSymbolAddress((void**)&p_srcs, g_srcs);
    cudaGetSymbolAddress((void**)&p_perm, g_perm);
    cudaGetSymbolAddress((void**)&p_gcnt, g_gcnt);
    cudaGetSymbolAddress((void**)&p_goff, g_goff);
    cudaGetSymbolAddress((void**)&p_bsums, g_bsums);

    int nbN = (nN + 1023) / 1024;
    int nbG = (nG + 1023) / 1024;
    int fused_blocks = (nN + FNB - 1) / FNB;

    // 0: zero, 1: hist, 2: scanN, 3: gemm64 (ncu window)
    zero_fused<<<(nN + 255) / 256, 256>>>(p_deg, p_cur, p_gcnt, nN, nG);
    hist_fused<<<(nE + 255) / 256, 256>>>(r2r_dst, graph_id, p_deg, p_gcnt, nE, nN);
    scan_block<<<nbN, 1024>>>(p_deg, p_off, p_bsums, nN);
    gemm64_kernel<<<592, 256>>>(r_node, W_r, nullptr, p_h, p_h16a,
                                a_s, a_d, p_hsa, p_hda, nN, 0);
    scan_sums_par<<<1, 128>>>(p_bsums, nbN);
    add_base<<<nbN, 1024>>>(p_off, p_bsums, nN);
    scan_block<<<nbG, 1024>>>(p_gcnt, p_goff, p_bsums, nG);
    scan_sums_par<<<1, 128>>>(p_bsums, nbG);
    add_base<<<nbG, 1024>>>(p_goff, p_bsums, nG);
    scatter_kernel<<<(nE + 255) / 256, 256>>>(r2r_src, r2r_dst, p_off, p_cur,
                                              p_perm, p_srcs, nE);
    build_recsr_kernel<<<(nE + 255) / 256, 256>>>(r_edge, p_perm, p_recsr, nE);

    // --- 4 fused attention+GEMM layers (double-buffered h16/hs/hd) ---
    for (int l = 0; l < LYR; l++) {
        const __half2* h16_in  = (l & 1) ? p_h16b : p_h16a;
        __half2*       h16_out = (l & 1) ? p_h16a : p_h16b;
        const float*   hs_in   = (l & 1) ? p_hsb : p_hsa;
        const float*   hd_in   = (l & 1) ? p_hdb : p_hda;
        float*         hs_out  = (l & 1) ? p_hsa : p_hsb;
        float*         hd_out  = (l & 1) ? p_hda : p_hdb;
        const float* as_next = (l < LYR - 1) ? (a_s + (l + 1) * H) : nullptr;
        const float* ad_next = (l < LYR - 1) ? (a_d + (l + 1) * H) : nullptr;
        fused_layer_kernel<<<fused_blocks, 256>>>(
            p_off, p_srcs, p_recsr, W_e, a_e, l, Wm + (size_t)l * H * H,
            hs_in, hd_in, h16_in, p_h, h16_out,
            as_next, ad_next, hs_out, hd_out, nN);
    }

    // --- fused pool + interaction + MLP (final h16 = buffer A after 4 layers) ---
    poolmlp_kernel<<<(nG + 7) / 8, 256>>>(p_goff, d_edge, w_d, b_d, i_node, W_i,
                                          p_h16a, W_mlp, b_mlp, W_out, b_out, out, nG);
}

// round 16
// speedup vs baseline: 1.3367x; 1.3367x over previous
#include <cuda_runtime.h>
#include <cuda_fp16.h>
#include <cstdint>

#define N_R   100000
#define N_E   1200000
#define G_N   4096
#define H     64
#define ED    16
#define LYR   4
#define NB    32
#define EMAX  512

// ---------------- scratch (device globals; allocation-free) ----------------
__device__ float   g_h[(size_t)N_R * H];
__device__ __half2 g_h16[(size_t)N_R * (H / 2)];
__device__ __half2 g_agg16[(size_t)N_R * (H / 2)];
__device__ float   g_hs[N_R];
__device__ float   g_hd[N_R];
__device__ uint4   g_recsr[(size_t)N_E * 2];
__device__ int     g_deg[N_R];
__device__ int     g_off[N_R + 1];
__device__ int     g_cur[N_R];
__device__ int     g_srcs[N_E];
__device__ int     g_gcnt[G_N];
__device__ int     g_goff[G_N + 1];
__device__ int     g_bsums[256];

__device__ __forceinline__ unsigned pack_half2(float a, float b) {
    __half2 h = __floats2half2_rn(a, b);
    return *reinterpret_cast<unsigned*>(&h);
}

// ---------------- fused setup kernels ----------------
__global__ void zero_fused(int* deg, int* cur, int* gcnt, int nN, int nG) {
    int i = blockIdx.x * blockDim.x + threadIdx.x;
    if (i < nN) { deg[i] = 0; cur[i] = 0; }
    if (i < nG) gcnt[i] = 0;
}
__global__ void hist_fused(const int* __restrict__ dst, const int* __restrict__ gid,
                           int* __restrict__ deg, int* __restrict__ gcnt,
                           int nE, int nN) {
    int i = blockIdx.x * blockDim.x + threadIdx.x;
    if (i < nE) atomicAdd(&deg[dst[i]], 1);
    if (i < nN) atomicAdd(&gcnt[gid[i]], 1);
}

// ---- multi-block exclusive scan (N) ----
__global__ void scan_block(const int* __restrict__ cnt, int* __restrict__ off,
                           int* __restrict__ sums, int n) {
    __shared__ int wsum[32];
    int tid = threadIdx.x;
    int i = blockIdx.x * 1024 + tid;
    int v = (i < n) ? cnt[i] : 0;
    int x = v;
    #pragma unroll
    for (int d = 1; d < 32; d <<= 1) {
        int y = __shfl_up_sync(0xffffffffu, x, d);
        if ((tid & 31) >= d) x += y;
    }
    if ((tid & 31) == 31) wsum[tid >> 5] = x;
    __syncthreads();
    if (tid < 32) {
        int w = wsum[tid];
        #pragma unroll
        for (int d = 1; d < 32; d <<= 1) {
            int y = __shfl_up_sync(0xffffffffu, w, d);
            if (tid >= d) w += y;
        }
        wsum[tid] = w;
    }
    __syncthreads();
    int incl = x + ((tid >= 32) ? wsum[(tid >> 5) - 1] : 0);
    if (i < n) off[i + 1] = incl;
    if (tid == 1023) sums[blockIdx.x] = incl;
}
__global__ void scan_sums_par(int* sums, int nb) {
    __shared__ int ws[4];
    int tid = threadIdx.x;
    int lane = tid & 31;
    int v = (tid < nb) ? sums[tid] : 0;
    int x = v;
    #pragma unroll
    for (int d = 1; d < 32; d <<= 1) {
        int y = __shfl_up_sync(0xffffffffu, x, d);
        if (lane >= d) x += y;
    }
    if (lane == 31) ws[tid >> 5] = x;
    __syncthreads();
    if (tid == 0) {
        int a = 0;
        #pragma unroll
        for (int j = 0; j < 4; j++) { int t = ws[j]; ws[j] = a; a += t; }
    }
    __syncthreads();
    x += ws[tid >> 5];
    if (tid < nb) sums[tid] = x - v;
}
__global__ void add_base(int* __restrict__ off, const int* __restrict__ sums, int n) {
    int i = blockIdx.x * 1024 + threadIdx.x;
    if (i == 0) off[0] = 0;
    if (i < n) off[i + 1] += sums[blockIdx.x];
}

// ---- single-block exclusive scan for goff (n <= 4096) ----
__global__ void scan_small(const int* __restrict__ cnt, int* __restrict__ off, int n) {
    __shared__ int wsum[32];
    __shared__ int s_base;
    int tid = threadIdx.x;
    if (tid == 0) { s_base = 0; off[0] = 0; }
    __syncthreads();
    for (int start = 0; start < n; start += 1024) {
        int i = start + tid;
        int v = (i < n) ? cnt[i] : 0;
        int x = v;
        #pragma unroll
        for (int d = 1; d < 32; d <<= 1) {
            int y = __shfl_up_sync(0xffffffffu, x, d);
            if ((tid & 31) >= d) x += y;
        }
        if ((tid & 31) == 31) wsum[tid >> 5] = x;
        __syncthreads();
        if (tid < 32) {
            int w = wsum[tid];
            #pragma unroll
            for (int d = 1; d < 32; d <<= 1) {
                int y = __shfl_up_sync(0xffffffffu, w, d);
                if (tid >= d) w += y;
            }
            wsum[tid] = w;
        }
        __syncthreads();
        int incl = s_base + x + ((tid >= 32) ? wsum[(tid >> 5) - 1] : 0);
        if (i < n) off[i + 1] = incl;
        __syncthreads();
        if (tid == 1023) s_base = incl;
        __syncthreads();
    }
}

// ---- scatter fused with recsr fp16 conversion (sequential r_edge read) ----
__global__ void scatter_recsr_kernel(const int* __restrict__ src, const int* __restrict__ dst,
                                     const float* __restrict__ r_edge,
                                     const int* __restrict__ off, int* __restrict__ cur,
                                     int* __restrict__ srcs, uint4* __restrict__ recsr,
                                     int n) {
    int e = blockIdx.x * blockDim.x + threadIdx.x;
    if (e >= n) return;
    int d = dst[e];
    int p = off[d] + atomicAdd(&cur[d], 1);
    srcs[p] = src[e];
    const float4* rp = (const float4*)(r_edge + (size_t)e * ED);
    float4 q0 = rp[0], q1 = rp[1], q2 = rp[2], q3 = rp[3];
    __half2 hv[8];
    hv[0] = __floats2half2_rn(q0.x, q0.y);
    hv[1] = __floats2half2_rn(q0.z, q0.w);
    hv[2] = __floats2half2_rn(q1.x, q1.y);
    hv[3] = __floats2half2_rn(q1.z, q1.w);
    hv[4] = __floats2half2_rn(q2.x, q2.y);
    hv[5] = __floats2half2_rn(q2.z, q2.w);
    hv[6] = __floats2half2_rn(q3.x, q3.y);
    hv[7] = __floats2half2_rn(q3.z, q3.w);
    recsr[(size_t)p * 2]     = *(uint4*)&hv[0];
    recsr[(size_t)p * 2 + 1] = *(uint4*)&hv[4];
}

// ---------------- tensor-core node GEMM (R14-proven dual-path) --------------
__global__ void __launch_bounds__(256)
gemm64_kernel(const float* __restrict__ in32, const __half2* __restrict__ in16,
              const float* __restrict__ W,
              const float* __restrict__ resid, float* __restrict__ out,
              __half2* __restrict__ out16,
              const float* __restrict__ as_, const float* __restrict__ ad_,
              float* __restrict__ hs, float* __restrict__ hd,
              int n, int do_lrelu) {
    __shared__ float  sW[64 * 64];
    __shared__ __half sA[64][72];
    __shared__ float  sRed[64][4];
    int tid = threadIdx.x;
    int lane = tid & 31;
    int w = tid >> 5;
    int wr = (w & 3) * 16;
    int cg = w >> 2;

    for (int i = tid; i < 4096; i += 256) sW[i] = W[i];
    __syncthreads();
    unsigned bfr[4][4][2];
    {
        int col = cg * 32 + (lane >> 2);
        int k0 = (lane & 3) * 2;
        #pragma unroll
        for (int f = 0; f < 4; f++) {
            int c = col + f * 8;
            #pragma unroll
            for (int s = 0; s < 4; s++) {
                int kk = s * 16 + k0;
                bfr[f][s][0] = pack_half2(sW[kk * 64 + c],       sW[(kk + 1) * 64 + c]);
                bfr[f][s][1] = pack_half2(sW[(kk + 8) * 64 + c], sW[(kk + 9) * 64 + c]);
            }
        }
    }

    float as0[8], ad0[8];
    if (as_) {
        #pragma unroll
        for (int f = 0; f < 4; f++) {
            int c = cg * 32 + f * 8 + 2 * (lane & 3);
            as0[2 * f]     = as_[c];     as0[2 * f + 1] = as_[c + 1];
            ad0[2 * f]     = ad_[c];     ad0[2 * f + 1] = ad_[c + 1];
        }
    }

    int ntiles = (n + 63) / 64;
    for (int t = blockIdx.x; t < ntiles; t += gridDim.x) {
        int base = t * 64;
        __syncthreads();
        if (in16) {
            for (int i = tid; i < 2048; i += 256) {
                int row = i >> 5;
                int k2 = i & 31;
                int node = base + row;
                __half2 v = (node < n) ? in16[(size_t)node * 32 + k2]
                                       : __floats2half2_rn(0.f, 0.f);
                *(__half2*)&sA[row][k2 * 2] = v;
            }
        } else {
            for (int i = tid; i < 2048; i += 256) {
                int row = i >> 5;
                int k0 = (i & 31) * 2;
                int node = base + row;
                float2 v = (node < n) ? *(const float2*)(in32 + (size_t)node * H + k0)
                                      : make_float2(0.f, 0.f);
                *(__half2*)&sA[row][k0] = __floats2half2_rn(v.x, v.y);
            }
        }
        __syncthreads();

        float c[4][4];
        #pragma unroll
        for (int f = 0; f < 4; f++)
            #pragma unroll
            for (int j = 0; j < 4; j++) c[f][j] = 0.f;

        int r = lane >> 2, k0 = (lane & 3) * 2;
        #pragma unroll
        for (int s = 0; s < 4; s++) {
            unsigned a0 = *(unsigned*)&sA[wr + r][s * 16 + k0];
            unsigned a1 = *(unsigned*)&sA[wr + r + 8][s * 16 + k0];
            unsigned a2 = *(unsigned*)&sA[wr + r][s * 16 + 8 + k0];
            unsigned a3 = *(unsigned*)&sA[wr + r + 8][s * 16 + 8 + k0];
            #pragma unroll
            for (int f = 0; f < 4; f++) {
                asm volatile(
                    "mma.sync.aligned.m16n8k16.row.col.f32.f16.f16.f32 "
                    "{%0,%1,%2,%3}, {%4,%5,%6,%7}, {%8,%9}, {%0,%1,%2,%3};"
                    : "+f"(c[f][0]), "+f"(c[f][1]), "+f"(c[f][2]), "+f"(c[f][3])
                    : "r"(a0), "r"(a1), "r"(a2), "r"(a3),
                      "r"(bfr[f][s][0]), "r"(bfr[f][s][1]));
            }
        }

        int rowA = wr + (lane >> 2);
        int rowB = rowA + 8;
        int nodeA = base + rowA;
        int nodeB = base + rowB;
        float psA = 0.f, pdA = 0.f, psB = 0.f, pdB = 0.f;
        #pragma unroll
        for (int f = 0; f < 4; f++) {
            int col = cg * 32 + f * 8 + 2 * (lane & 3);
            float v0 = c[f][0], v1 = c[f][1];
            float u0 = c[f][2], u1 = c[f][3];
            if (resid) {
                if (nodeA < n) {
                    float2 rr = *(const float2*)(resid + (size_t)nodeA * H + col);
                    v0 += rr.x; v1 += rr.y;
                }
                if (nodeB < n) {
                    float2 rr = *(const float2*)(resid + (size_t)nodeB * H + col);
                    u0 += rr.x; u1 += rr.y;
                }
            }
            if (do_lrelu) {
                v0 = v0 > 0.f ? v0 : 0.1f * v0;  v1 = v1 > 0.f ? v1 : 0.1f * v1;
                u0 = u0 > 0.f ? u0 : 0.1f * u0;  u1 = u1 > 0.f ? u1 : 0.1f * u1;
            }
            if (nodeA < n) {
                *(float2*)(out + (size_t)nodeA * H + col) = make_float2(v0, v1);
                out16[(size_t)nodeA * 32 + (col >> 1)] = __floats2half2_rn(v0, v1);
            }
            if (nodeB < n) {
                *(float2*)(out + (size_t)nodeB * H + col) = make_float2(u0, u1);
                out16[(size_t)nodeB * 32 + (col >> 1)] = __floats2half2_rn(u0, u1);
            }
            if (as_) {
                psA += v0 * as0[2 * f] + v1 * as0[2 * f + 1];
                pdA += v0 * ad0[2 * f] + v1 * ad0[2 * f + 1];
                psB += u0 * as0[2 * f] + u1 * as0[2 * f + 1];
                pdB += u0 * ad0[2 * f] + u1 * ad0[2 * f + 1];
            }
        }
        if (as_) {
            #pragma unroll
            for (int d = 1; d < 4; d <<= 1) {
                psA += __shfl_xor_sync(0xffffffffu, psA, d);
                pdA += __shfl_xor_sync(0xffffffffu, pdA, d);
                psB += __shfl_xor_sync(0xffffffffu, psB, d);
                pdB += __shfl_xor_sync(0xffffffffu, pdB, d);
            }
            if ((lane & 3) == 0) {
                sRed[rowA][cg * 2 + 0] = psA;  sRed[rowA][cg * 2 + 1] = pdA;
                sRed[rowB][cg * 2 + 0] = psB;  sRed[rowB][cg * 2 + 1] = pdB;
            }
            __syncthreads();
            if (tid < 64 && base + tid < n) {
                hs[base + tid] = sRed[tid][0] + sRed[tid][2];
                hd[base + tid] = sRed[tid][1] + sRed[tid][3];
            }
        }
    }
}

// ---------------- block-cooperative attention layer (R14-proven) -------------
__global__ void __launch_bounds__(256)
layer_kernel(const int* __restrict__ off, const int* __restrict__ srcs,
             const uint4* __restrict__ recsr,
             const float* __restrict__ W_e, const float* __restrict__ a_e, int l,
             const float* __restrict__ hs, const float* __restrict__ hd,
             const __half2* __restrict__ h16,
             __half2* __restrict__ agg16, int n) {
    __shared__ float  sWe[ED * H];
    __shared__ float  sw16[ED];
    __shared__ int    s_off[NB + 1];
    __shared__ float  s_hd[NB];
    __shared__ float  s_sum[NB];
    __shared__ float  s_w[EMAX];
    __shared__ int    s_src[EMAX];
    __shared__ uint4  s_re[EMAX * 2];
    int tid = threadIdx.x, lane = tid & 31, w = tid >> 5;
    int node0 = blockIdx.x * NB;
    for (int i = tid; i < ED * H; i += 256) sWe[i] = W_e[i];
    if (tid <= NB) {
        int nd = node0 + tid;
        s_off[tid] = off[nd <= n ? nd : n];
    }
    if (tid < NB) {
        s_sum[tid] = 0.f;
        int nd = node0 + tid;
        s_hd[tid] = (nd < n) ? hd[nd] : 0.f;
    }
    __syncthreads();
    if (tid < ED) {
        float s = 0.f;
        const float* ae = a_e + l * H;
        #pragma unroll 8
        for (int j = 0; j < H; j++) s += sWe[tid * H + j] * ae[j];
        sw16[tid] = s;
    }
    __syncthreads();

    int base = s_off[0], endall = s_off[NB];
    float acc[4][2] = {{0.f,0.f},{0.f,0.f},{0.f,0.f},{0.f,0.f}};
    float acc16[4] = {0.f, 0.f, 0.f, 0.f};

    for (int cs = base; cs < endall; cs += EMAX) {
        int cnt = min(EMAX, endall - cs);
        for (int i = tid; i < cnt; i += 256) {
            int p = cs + i;
            int sv = __ldg(&srcs[p]);
            uint4 ra = __ldg(&recsr[(size_t)p * 2]);
            uint4 rb = __ldg(&recsr[(size_t)p * 2 + 1]);
            const __half2* ha = (const __half2*)&ra;
            const __half2* hb = (const __half2*)&rb;
            float ea = 0.f;
            #pragma unroll
            for (int j = 0; j < 4; j++) {
                float2 f = __half22float2(ha[j]);
                ea += f.x * sw16[2 * j] + f.y * sw16[2 * j + 1];
            }
            #pragma unroll
            for (int j = 0; j < 4; j++) {
                float2 f = __half22float2(hb[j]);
                ea += f.x * sw16[8 + 2 * j] + f.y * sw16[8 + 2 * j + 1];
            }
            int lo = 0, hi = NB;
            #pragma unroll
            for (int b = 0; b < 5; b++) {
                int mid = (lo + hi) >> 1;
                bool ge = (p >= s_off[mid]);
                lo = ge ? mid : lo;
                hi = ge ? hi : mid;
            }
            float lg = __ldg(&hs[sv]) + s_hd[lo] + ea;
            lg = lg > 0.f ? lg : 0.1f * lg;
            float ew = __expf(fminf(lg, 85.f));
            s_w[i] = ew;
            s_src[i] = sv;
            s_re[i * 2]     = ra;
            s_re[i * 2 + 1] = rb;
            atomicAdd(&s_sum[lo], ew);
        }
        __syncthreads();
        const __half* s_reh = (const __half*)s_re;
        #pragma unroll
        for (int j = 0; j < 4; j++) {
            int ndl = w * 4 + j;
            int lo = max(s_off[ndl], cs) - cs;
            int hi = min(s_off[ndl + 1], cs + cnt) - cs;
            #pragma unroll 4
            for (int i = lo; i < hi; i++) {
                float wv = s_w[i];
                int sv = s_src[i];
                float2 hp = __half22float2(h16[(size_t)sv * 32 + lane]);
                acc[j][0] += wv * hp.x;
                acc[j][1] += wv * hp.y;
                if (lane < ED)
                    acc16[j] += wv * __half2float(s_reh[i * ED + lane]);
            }
        }
        __syncthreads();
    }
    #pragma unroll
    for (int j = 0; j < 4; j++) {
        int ndl = w * 4 + j;
        int nd = node0 + ndl;
        float a0 = acc[j][0], a1 = acc[j][1];
        #pragma unroll
        for (int k = 0; k < ED; k++) {
            float b = __shfl_sync(0xffffffffu, acc16[j], k);
            a0 += b * sWe[k * H + 2 * lane];
            a1 += b * sWe[k * H + 2 * lane + 1];
        }
        if (nd < n) {
            float s = s_sum[ndl];
            float inv = (s > 0.f) ? (1.0f / s) : 0.f;
            agg16[(size_t)nd * 32 + lane] = __floats2half2_rn(a0 * inv, a1 * inv);
        }
    }
}

// ---------------- fused pool + interaction + MLP readout (h16 input) --------
__global__ void __launch_bounds__(256)
poolmlp_kernel(const int* __restrict__ goff, const float* __restrict__ d_edge,
               const float* __restrict__ w_d, const float* __restrict__ b_d,
               const float* __restrict__ i_node, const float* __restrict__ W_i,
               const __half2* __restrict__ h16,
               const float* __restrict__ W_mlp, const float* __restrict__ b_mlp,
               const float* __restrict__ W_out, const float* __restrict__ b_out,
               float* __restrict__ out, int g_total) {
    __shared__ float sW[3 * 4096];
    __shared__ float sb[3 * 64];
    __shared__ float sWo[64];
    __shared__ float sx[8][64];
    int tid = threadIdx.x, lane = tid & 31, wl = tid >> 5;
    for (int i = tid; i < 3 * 4096; i += 256) sW[i] = W_mlp[i];
    if (tid < 192) sb[tid] = b_mlp[tid];
    if (tid < 64) sWo[tid] = W_out[tid];
    __syncthreads();
    float wd = w_d[0], bd = b_d[0], bo = b_out[0];
    int g = blockIdx.x * 8 + wl;
    if (g >= g_total) return;

    int beg = goff[g], end = goff[g + 1];
    float s00 = 0.f, s01 = 0.f, s10 = 0.f, s11 = 0.f, sg = 0.f;
    for (int nn = beg; nn < end; nn++) {
        float gate = 1.0f / (1.0f + __expf(-(d_edge[nn] * wd + bd)));
        float2 hp = __half22float2(h16[(size_t)nn * 32 + lane]);
        s00 += hp.x; s01 += hp.y;
        s10 += gate * hp.x; s11 += gate * hp.y;
        sg += gate;
    }
    float iv = i_node[g];
    float hi0 = iv * W_i[2 * lane] + s10;
    float hi1 = iv * W_i[2 * lane + 1] + s11;
    sx[wl][2 * lane]     = s00 + sg * hi0;
    sx[wl][2 * lane + 1] = s01 + sg * hi1;
    __syncwarp();

    for (int l = 0; l < 3; l++) {
        float a0 = sb[l * 64 + 2 * lane];
        float a1 = sb[l * 64 + 2 * lane + 1];
        const float* Wl = sW + l * 4096;
        #pragma unroll 8
        for (int k = 0; k < 64; k++) {
            float xv = sx[wl][k];
            a0 += xv * Wl[k * 64 + 2 * lane];
            a1 += xv * Wl[k * 64 + 2 * lane + 1];
        }
        a0 = fmaxf(a0, 0.f);
        a1 = fmaxf(a1, 0.f);
        __syncwarp();
        sx[wl][2 * lane]     = a0;
        sx[wl][2 * lane + 1] = a1;
        __syncwarp();
    }
    float part = sx[wl][2 * lane] * sWo[2 * lane] + sx[wl][2 * lane + 1] * sWo[2 * lane + 1];
    #pragma unroll
    for (int d = 16; d; d >>= 1) part += __shfl_xor_sync(0xffffffffu, part, d);
    if (lane == 0) out[g] = part + bo;
}

// ---------------- launcher ----------------
extern "C" void kernel_launch(void* const* d_in, const int* in_sizes, int n_in,
                              void* d_out, int out_size) {
    const float* r_node  = (const float*)d_in[0];
    const float* i_node  = (const float*)d_in[1];
    const float* r_edge  = (const float*)d_in[2];
    const float* d_edge  = (const float*)d_in[3];
    const int*   r2r_src = (const int*)d_in[4];
    const int*   r2r_dst = (const int*)d_in[5];
    const int*   graph_id= (const int*)d_in[6];
    const float* W_r     = (const float*)d_in[7];
    const float* W_i     = (const float*)d_in[8];
    const float* W_e     = (const float*)d_in[9];
    const float* Wm      = (const float*)d_in[10];
    const float* a_s     = (const float*)d_in[11];
    const float* a_d     = (const float*)d_in[12];
    const float* a_e     = (const float*)d_in[13];
    const float* w_d     = (const float*)d_in[14];
    const float* b_d     = (const float*)d_in[15];
    const float* W_mlp   = (const float*)d_in[16];
    const float* b_mlp   = (const float*)d_in[17];
    const float* W_out   = (const float*)d_in[18];
    const float* b_out   = (const float*)d_in[19];
    float* out = (float*)d_out;

    const int nN = in_sizes[3];
    const int nE = in_sizes[4];
    const int nG = in_sizes[1];

    float *p_h, *p_hs, *p_hd;
    __half2 *p_h16, *p_agg16;
    uint4*   p_recsr;
    int *p_deg, *p_off, *p_cur, *p_srcs, *p_gcnt, *p_goff, *p_bsums;
    cudaGetSymbolAddress((void**)&p_h, g_h);
    cudaGetSymbolAddress((void**)&p_h16, g_h16);
    cudaGetSymbolAddress((void**)&p_agg16, g_agg16);
    cudaGetSymbolAddress((void**)&p_hs, g_hs);
    cudaGetSymbolAddress((void**)&p_hd, g_hd);
    cudaGetSymbolAddress((void**)&p_recsr, g_recsr);
    cudaGetSymbolAddress((void**)&p_deg, g_deg);
    cudaGetSymbolAddress((void**)&p_off, g_off);
    cudaGetSymbolAddress((void**)&p_cur, g_cur);
    cudaGetSymbolAddress((void**)&p_srcs, g_srcs);
    cudaGetSymbolAddress((void**)&p_gcnt, g_gcnt);
    cudaGetSymbolAddress((void**)&p_goff, g_goff);
    cudaGetSymbolAddress((void**)&p_bsums, g_bsums);

    int nbN = (nN + 1023) / 1024;
    int layer_blocks = (nN + NB - 1) / NB;

    // 0: zero, 1: hist, 2: scanN, 3: gemm64 (ncu window)
    zero_fused<<<(nN + 255) / 256, 256>>>(p_deg, p_cur, p_gcnt, nN, nG);
    hist_fused<<<(nE + 255) / 256, 256>>>(r2r_dst, graph_id, p_deg, p_gcnt, nE, nN);
    scan_block<<<nbN, 1024>>>(p_deg, p_off, p_bsums, nN);
    gemm64_kernel<<<592, 256>>>(r_node, nullptr, W_r, nullptr, p_h, p_h16,
                                a_s, a_d, p_hs, p_hd, nN, 0);
    scan_sums_par<<<1, 128>>>(p_bsums, nbN);
    add_base<<<nbN, 1024>>>(p_off, p_bsums, nN);
    scan_small<<<1, 1024>>>(p_gcnt, p_goff, nG);
    scatter_recsr_kernel<<<(nE + 255) / 256, 256>>>(r2r_src, r2r_dst, r_edge,
                                                    p_off, p_cur, p_srcs, p_recsr, nE);

    // --- 4 attention conv layers ---
    for (int l = 0; l < LYR; l++) {
        layer_kernel<<<layer_blocks, 256>>>(p_off, p_srcs, p_recsr, W_e, a_e, l,
                                            p_hs, p_hd, p_h16, p_agg16, nN);
        const float* as_next = (l < LYR - 1) ? (a_s + (l + 1) * H) : nullptr;
        const float* ad_next = (l < LYR - 1) ? (a_d + (l + 1) * H) : nullptr;
        gemm64_kernel<<<592, 256>>>(nullptr, p_agg16, Wm + (size_t)l * H * H,
                                    p_h, p_h, p_h16,
                                    as_next, ad_next, p_hs, p_hd, nN, 1);
    }

    // --- fused pool + interaction + MLP ---
    poolmlp_kernel<<<(nG + 7) / 8, 256>>>(p_goff, d_edge, w_d, b_d, i_node, W_i,
                                          p_h16, W_mlp, b_mlp, W_out, b_out, out, nG);
}

// round 17
// speedup vs baseline: 1.3623x; 1.0192x over previous
#include <cuda_runtime.h>
#include <cuda_fp16.h>
#include <cstdint>

#define N_R   100000
#define N_E   1200000
#define G_N   4096
#define H     64
#define ED    16
#define LYR   4
#define NB    32
#define EMAX  512

// ---------------- scratch (device globals; allocation-free) ----------------
__device__ float   g_h[(size_t)N_R * H];
__device__ __half2 g_h16[(size_t)N_R * (H / 2)];
__device__ __half2 g_agg16[(size_t)N_R * (H / 2)];
__device__ float   g_hs[N_R];
__device__ float   g_hd[N_R];
__device__ uint4   g_recsr[(size_t)N_E * 2];
__device__ int     g_deg[N_R];
__device__ int     g_off[N_R + 1];
__device__ int     g_cur[N_R];
__device__ int     g_srcs[N_E];
__device__ int     g_gcnt[G_N];
__device__ int     g_goff[G_N + 1];
__device__ int     g_bsums[256];

__device__ __forceinline__ unsigned pack_half2(float a, float b) {
    __half2 h = __floats2half2_rn(a, b);
    return *reinterpret_cast<unsigned*>(&h);
}

// ---------------- fused setup kernels ----------------
__global__ void zero_fused(int* deg, int* cur, int* gcnt, int nN, int nG) {
    int i = blockIdx.x * blockDim.x + threadIdx.x;
    if (i < nN) { deg[i] = 0; cur[i] = 0; }
    if (i < nG) gcnt[i] = 0;
}
__global__ void hist_fused(const int* __restrict__ dst, const int* __restrict__ gid,
                           int* __restrict__ deg, int* __restrict__ gcnt,
                           int nE, int nN) {
    int i = blockIdx.x * blockDim.x + threadIdx.x;
    if (i < nE) atomicAdd(&deg[dst[i]], 1);
    if (i < nN) atomicAdd(&gcnt[gid[i]], 1);
}

// ---- multi-block exclusive scan (N) ----
__global__ void scan_block(const int* __restrict__ cnt, int* __restrict__ off,
                           int* __restrict__ sums, int n) {
    __shared__ int wsum[32];
    int tid = threadIdx.x;
    int i = blockIdx.x * 1024 + tid;
    int v = (i < n) ? cnt[i] : 0;
    int x = v;
    #pragma unroll
    for (int d = 1; d < 32; d <<= 1) {
        int y = __shfl_up_sync(0xffffffffu, x, d);
        if ((tid & 31) >= d) x += y;
    }
    if ((tid & 31) == 31) wsum[tid >> 5] = x;
    __syncthreads();
    if (tid < 32) {
        int w = wsum[tid];
        #pragma unroll
        for (int d = 1; d < 32; d <<= 1) {
            int y = __shfl_up_sync(0xffffffffu, w, d);
            if (tid >= d) w += y;
        }
        wsum[tid] = w;
    }
    __syncthreads();
    int incl = x + ((tid >= 32) ? wsum[(tid >> 5) - 1] : 0);
    if (i < n) off[i + 1] = incl;
    if (tid == 1023) sums[blockIdx.x] = incl;
}
__global__ void scan_sums_par(int* sums, int nb) {
    __shared__ int ws[4];
    int tid = threadIdx.x;
    int lane = tid & 31;
    int v = (tid < nb) ? sums[tid] : 0;
    int x = v;
    #pragma unroll
    for (int d = 1; d < 32; d <<= 1) {
        int y = __shfl_up_sync(0xffffffffu, x, d);
        if (lane >= d) x += y;
    }
    if (lane == 31) ws[tid >> 5] = x;
    __syncthreads();
    if (tid == 0) {
        int a = 0;
        #pragma unroll
        for (int j = 0; j < 4; j++) { int t = ws[j]; ws[j] = a; a += t; }
    }
    __syncthreads();
    x += ws[tid >> 5];
    if (tid < nb) sums[tid] = x - v;
}
__global__ void add_base(int* __restrict__ off, const int* __restrict__ sums, int n) {
    int i = blockIdx.x * 1024 + threadIdx.x;
    if (i == 0) off[0] = 0;
    if (i < n) off[i + 1] += sums[blockIdx.x];
}

// ---- single-block exclusive scan for goff (n <= 4096) ----
__global__ void scan_small(const int* __restrict__ cnt, int* __restrict__ off, int n) {
    __shared__ int wsum[32];
    __shared__ int s_base;
    int tid = threadIdx.x;
    if (tid == 0) { s_base = 0; off[0] = 0; }
    __syncthreads();
    for (int start = 0; start < n; start += 1024) {
        int i = start + tid;
        int v = (i < n) ? cnt[i] : 0;
        int x = v;
        #pragma unroll
        for (int d = 1; d < 32; d <<= 1) {
            int y = __shfl_up_sync(0xffffffffu, x, d);
            if ((tid & 31) >= d) x += y;
        }
        if ((tid & 31) == 31) wsum[tid >> 5] = x;
        __syncthreads();
        if (tid < 32) {
            int w = wsum[tid];
            #pragma unroll
            for (int d = 1; d < 32; d <<= 1) {
                int y = __shfl_up_sync(0xffffffffu, w, d);
                if (tid >= d) w += y;
            }
            wsum[tid] = w;
        }
        __syncthreads();
        int incl = s_base + x + ((tid >= 32) ? wsum[(tid >> 5) - 1] : 0);
        if (i < n) off[i + 1] = incl;
        __syncthreads();
        if (tid == 1023) s_base = incl;
        __syncthreads();
    }
}

// ---- scatter fused with recsr fp16 conversion ----
__global__ void scatter_recsr_kernel(const int* __restrict__ src, const int* __restrict__ dst,
                                     const float* __restrict__ r_edge,
                                     const int* __restrict__ off, int* __restrict__ cur,
                                     int* __restrict__ srcs, uint4* __restrict__ recsr,
                                     int n) {
    int e = blockIdx.x * blockDim.x + threadIdx.x;
    if (e >= n) return;
    int d = dst[e];
    int p = off[d] + atomicAdd(&cur[d], 1);
    srcs[p] = src[e];
    const float4* rp = (const float4*)(r_edge + (size_t)e * ED);
    float4 q0 = rp[0], q1 = rp[1], q2 = rp[2], q3 = rp[3];
    __half2 hv[8];
    hv[0] = __floats2half2_rn(q0.x, q0.y);
    hv[1] = __floats2half2_rn(q0.z, q0.w);
    hv[2] = __floats2half2_rn(q1.x, q1.y);
    hv[3] = __floats2half2_rn(q1.z, q1.w);
    hv[4] = __floats2half2_rn(q2.x, q2.y);
    hv[5] = __floats2half2_rn(q2.z, q2.w);
    hv[6] = __floats2half2_rn(q3.x, q3.y);
    hv[7] = __floats2half2_rn(q3.z, q3.w);
    recsr[(size_t)p * 2]     = *(uint4*)&hv[0];
    recsr[(size_t)p * 2 + 1] = *(uint4*)&hv[4];
}

// ---------------- tensor-core node GEMM: templated + double-buffered --------
template<bool IN16>
__global__ void __launch_bounds__(256)
gemm64_t(const float* __restrict__ in32, const __half2* __restrict__ in16,
         const float* __restrict__ W,
         const float* __restrict__ resid, float* __restrict__ out,
         __half2* __restrict__ out16,
         const float* __restrict__ as_, const float* __restrict__ ad_,
         float* __restrict__ hs, float* __restrict__ hd,
         int n, int do_lrelu) {
    __shared__ float  sW[64 * 64];        // 16 KB
    __shared__ __half sA[2][64][72];      // 18.4 KB double buffer
    __shared__ float  sRed[64][4];
    int tid = threadIdx.x;
    int lane = tid & 31;
    int w = tid >> 5;
    int wr = (w & 3) * 16;
    int cg = w >> 2;

    for (int i = tid; i < 4096; i += 256) sW[i] = W[i];
    __syncthreads();
    unsigned bfr[4][4][2];
    {
        int col = cg * 32 + (lane >> 2);
        int k0 = (lane & 3) * 2;
        #pragma unroll
        for (int f = 0; f < 4; f++) {
            int c = col + f * 8;
            #pragma unroll
            for (int s = 0; s < 4; s++) {
                int kk = s * 16 + k0;
                bfr[f][s][0] = pack_half2(sW[kk * 64 + c],       sW[(kk + 1) * 64 + c]);
                bfr[f][s][1] = pack_half2(sW[(kk + 8) * 64 + c], sW[(kk + 9) * 64 + c]);
            }
        }
    }

    float as0[8], ad0[8];
    if (as_) {
        #pragma unroll
        for (int f = 0; f < 4; f++) {
            int c = cg * 32 + f * 8 + 2 * (lane & 3);
            as0[2 * f]     = as_[c];     as0[2 * f + 1] = as_[c + 1];
            ad0[2 * f]     = ad_[c];     ad0[2 * f + 1] = ad_[c + 1];
        }
    }

    int ntiles = (n + 63) / 64;
    int t = blockIdx.x;
    // prologue: load first tile into buffer 0
    if (t < ntiles) {
        int base = t * 64;
        #pragma unroll
        for (int j = 0; j < 8; j++) {
            int i = tid + j * 256;
            int row = i >> 5, k2 = i & 31;
            int node = base + row;
            __half2 v;
            if (IN16) v = (node < n) ? in16[(size_t)node * 32 + k2]
                                     : __floats2half2_rn(0.f, 0.f);
            else {
                float2 f = (node < n) ? *(const float2*)(in32 + (size_t)node * H + k2 * 2)
                                      : make_float2(0.f, 0.f);
                v = __floats2half2_rn(f.x, f.y);
            }
            *(__half2*)&sA[0][row][k2 * 2] = v;
        }
    }
    __syncthreads();
    int buf = 0;

    while (t < ntiles) {
        int tn = t + gridDim.x;
        // prefetch next tile into registers (LDG overlaps MMA below)
        __half2 pre[8];
        if (tn < ntiles) {
            int baseN = tn * 64;
            #pragma unroll
            for (int j = 0; j < 8; j++) {
                int i = tid + j * 256;
                int row = i >> 5, k2 = i & 31;
                int node = baseN + row;
                if (IN16) pre[j] = (node < n) ? in16[(size_t)node * 32 + k2]
                                              : __floats2half2_rn(0.f, 0.f);
                else {
                    float2 f = (node < n) ? *(const float2*)(in32 + (size_t)node * H + k2 * 2)
                                          : make_float2(0.f, 0.f);
                    pre[j] = __floats2half2_rn(f.x, f.y);
                }
            }
        }

        // MMA from sA[buf]
        float c[4][4];
        #pragma unroll
        for (int f = 0; f < 4; f++)
            #pragma unroll
            for (int j = 0; j < 4; j++) c[f][j] = 0.f;
        {
            int r = lane >> 2, k0 = (lane & 3) * 2;
            #pragma unroll
            for (int s = 0; s < 4; s++) {
                unsigned a0 = *(unsigned*)&sA[buf][wr + r][s * 16 + k0];
                unsigned a1 = *(unsigned*)&sA[buf][wr + r + 8][s * 16 + k0];
                unsigned a2 = *(unsigned*)&sA[buf][wr + r][s * 16 + 8 + k0];
                unsigned a3 = *(unsigned*)&sA[buf][wr + r + 8][s * 16 + 8 + k0];
                #pragma unroll
                for (int f = 0; f < 4; f++) {
                    asm volatile(
                        "mma.sync.aligned.m16n8k16.row.col.f32.f16.f16.f32 "
                        "{%0,%1,%2,%3}, {%4,%5,%6,%7}, {%8,%9}, {%0,%1,%2,%3};"
                        : "+f"(c[f][0]), "+f"(c[f][1]), "+f"(c[f][2]), "+f"(c[f][3])
                        : "r"(a0), "r"(a1), "r"(a2), "r"(a3),
                          "r"(bfr[f][s][0]), "r"(bfr[f][s][1]));
                }
            }
        }

        // epilogue for tile t
        int base = t * 64;
        int rowA = wr + (lane >> 2);
        int rowB = rowA + 8;
        int nodeA = base + rowA;
        int nodeB = base + rowB;
        float psA = 0.f, pdA = 0.f, psB = 0.f, pdB = 0.f;
        #pragma unroll
        for (int f = 0; f < 4; f++) {
            int col = cg * 32 + f * 8 + 2 * (lane & 3);
            float v0 = c[f][0], v1 = c[f][1];
            float u0 = c[f][2], u1 = c[f][3];
            if (resid) {
                if (nodeA < n) {
                    float2 rr = *(const float2*)(resid + (size_t)nodeA * H + col);
                    v0 += rr.x; v1 += rr.y;
                }
                if (nodeB < n) {
                    float2 rr = *(const float2*)(resid + (size_t)nodeB * H + col);
                    u0 += rr.x; u1 += rr.y;
                }
            }
            if (do_lrelu) {
                v0 = v0 > 0.f ? v0 : 0.1f * v0;  v1 = v1 > 0.f ? v1 : 0.1f * v1;
                u0 = u0 > 0.f ? u0 : 0.1f * u0;  u1 = u1 > 0.f ? u1 : 0.1f * u1;
            }
            if (nodeA < n) {
                *(float2*)(out + (size_t)nodeA * H + col) = make_float2(v0, v1);
                out16[(size_t)nodeA * 32 + (col >> 1)] = __floats2half2_rn(v0, v1);
            }
            if (nodeB < n) {
                *(float2*)(out + (size_t)nodeB * H + col) = make_float2(u0, u1);
                out16[(size_t)nodeB * 32 + (col >> 1)] = __floats2half2_rn(u0, u1);
            }
            if (as_) {
                psA += v0 * as0[2 * f] + v1 * as0[2 * f + 1];
                pdA += v0 * ad0[2 * f] + v1 * ad0[2 * f + 1];
                psB += u0 * as0[2 * f] + u1 * as0[2 * f + 1];
                pdB += u0 * ad0[2 * f] + u1 * ad0[2 * f + 1];
            }
        }
        if (as_) {
            #pragma unroll
            for (int d = 1; d < 4; d <<= 1) {
                psA += __shfl_xor_sync(0xffffffffu, psA, d);
                pdA += __shfl_xor_sync(0xffffffffu, pdA, d);
                psB += __shfl_xor_sync(0xffffffffu, psB, d);
                pdB += __shfl_xor_sync(0xffffffffu, pdB, d);
            }
            if ((lane & 3) == 0) {
                sRed[rowA][cg * 2 + 0] = psA;  sRed[rowA][cg * 2 + 1] = pdA;
                sRed[rowB][cg * 2 + 0] = psB;  sRed[rowB][cg * 2 + 1] = pdB;
            }
            __syncthreads();
            if (tid < 64 && base + tid < n) {
                hs[base + tid] = sRed[tid][0] + sRed[tid][2];
                hd[base + tid] = sRed[tid][1] + sRed[tid][3];
            }
        }

        // store prefetched tile into the other buffer, then sync
        if (tn < ntiles) {
            #pragma unroll
            for (int j = 0; j < 8; j++) {
                int i = tid + j * 256;
                int row = i >> 5, k2 = i & 31;
                *(__half2*)&sA[buf ^ 1][row][k2 * 2] = pre[j];
            }
        }
        __syncthreads();
        t = tn;
        buf ^= 1;
    }
}

// ---------------- block-cooperative attention layer (R14/16-proven) ----------
__global__ void __launch_bounds__(256)
layer_kernel(const int* __restrict__ off, const int* __restrict__ srcs,
             const uint4* __restrict__ recsr,
             const float* __restrict__ W_e, const float* __restrict__ a_e, int l,
             const float* __restrict__ hs, const float* __restrict__ hd,
             const __half2* __restrict__ h16,
             __half2* __restrict__ agg16, int n) {
    __shared__ float  sWe[ED * H];
    __shared__ float  sw16[ED];
    __shared__ int    s_off[NB + 1];
    __shared__ float  s_hd[NB];
    __shared__ float  s_sum[NB];
    __shared__ float  s_w[EMAX];
    __shared__ int    s_src[EMAX];
    __shared__ uint4  s_re[EMAX * 2];
    int tid = threadIdx.x, lane = tid & 31, w = tid >> 5;
    int node0 = blockIdx.x * NB;
    for (int i = tid; i < ED * H; i += 256) sWe[i] = W_e[i];
    if (tid <= NB) {
        int nd = node0 + tid;
        s_off[tid] = off[nd <= n ? nd : n];
    }
    if (tid < NB) {
        s_sum[tid] = 0.f;
        int nd = node0 + tid;
        s_hd[tid] = (nd < n) ? hd[nd] : 0.f;
    }
    __syncthreads();
    if (tid < ED) {
        float s = 0.f;
        const float* ae = a_e + l * H;
        #pragma unroll 8
        for (int j = 0; j < H; j++) s += sWe[tid * H + j] * ae[j];
        sw16[tid] = s;
    }
    __syncthreads();

    int base = s_off[0], endall = s_off[NB];
    float acc[4][2] = {{0.f,0.f},{0.f,0.f},{0.f,0.f},{0.f,0.f}};
    float acc16[4] = {0.f, 0.f, 0.f, 0.f};

    for (int cs = base; cs < endall; cs += EMAX) {
        int cnt = min(EMAX, endall - cs);
        for (int i = tid; i < cnt; i += 256) {
            int p = cs + i;
            int sv = __ldg(&srcs[p]);
            uint4 ra = __ldg(&recsr[(size_t)p * 2]);
            uint4 rb = __ldg(&recsr[(size_t)p * 2 + 1]);
            const __half2* ha = (const __half2*)&ra;
            const __half2* hb = (const __half2*)&rb;
            float ea = 0.f;
            #pragma unroll
            for (int j = 0; j < 4; j++) {
                float2 f = __half22float2(ha[j]);
                ea += f.x * sw16[2 * j] + f.y * sw16[2 * j + 1];
            }
            #pragma unroll
            for (int j = 0; j < 4; j++) {
                float2 f = __half22float2(hb[j]);
                ea += f.x * sw16[8 + 2 * j] + f.y * sw16[8 + 2 * j + 1];
            }
            int lo = 0, hi = NB;
            #pragma unroll
            for (int b = 0; b < 5; b++) {
                int mid = (lo + hi) >> 1;
                bool ge = (p >= s_off[mid]);
                lo = ge ? mid : lo;
                hi = ge ? hi : mid;
            }
            float lg = __ldg(&hs[sv]) + s_hd[lo] + ea;
            lg = lg > 0.f ? lg : 0.1f * lg;
            float ew = __expf(fminf(lg, 85.f));
            s_w[i] = ew;
            s_src[i] = sv;
            s_re[i * 2]     = ra;
            s_re[i * 2 + 1] = rb;
            atomicAdd(&s_sum[lo], ew);
        }
        __syncthreads();
        const __half* s_reh = (const __half*)s_re;
        #pragma unroll
        for (int j = 0; j < 4; j++) {
            int ndl = w * 4 + j;
            int lo = max(s_off[ndl], cs) - cs;
            int hi = min(s_off[ndl + 1], cs + cnt) - cs;
            #pragma unroll 4
            for (int i = lo; i < hi; i++) {
                float wv = s_w[i];
                int sv = s_src[i];
                float2 hp = __half22float2(h16[(size_t)sv * 32 + lane]);
                acc[j][0] += wv * hp.x;
                acc[j][1] += wv * hp.y;
                if (lane < ED)
                    acc16[j] += wv * __half2float(s_reh[i * ED + lane]);
            }
        }
        __syncthreads();
    }
    #pragma unroll
    for (int j = 0; j < 4; j++) {
        int ndl = w * 4 + j;
        int nd = node0 + ndl;
        float a0 = acc[j][0], a1 = acc[j][1];
        #pragma unroll
        for (int k = 0; k < ED; k++) {
            float b = __shfl_sync(0xffffffffu, acc16[j], k);
            a0 += b * sWe[k * H + 2 * lane];
            a1 += b * sWe[k * H + 2 * lane + 1];
        }
        if (nd < n) {
            float s = s_sum[ndl];
            float inv = (s > 0.f) ? (1.0f / s) : 0.f;
            agg16[(size_t)nd * 32 + lane] = __floats2half2_rn(a0 * inv, a1 * inv);
        }
    }
}

// ---------------- fused pool + interaction + MLP readout (h16 input) --------
__global__ void __launch_bounds__(256)
poolmlp_kernel(const int* __restrict__ goff, const float* __restrict__ d_edge,
               const float* __restrict__ w_d, const float* __restrict__ b_d,
               const float* __restrict__ i_node, const float* __restrict__ W_i,
               const __half2* __restrict__ h16,
               const float* __restrict__ W_mlp, const float* __restrict__ b_mlp,
               const float* __restrict__ W_out, const float* __restrict__ b_out,
               float* __restrict__ out, int g_total) {
    __shared__ float sW[3 * 4096];
    __shared__ float sb[3 * 64];
    __shared__ float sWo[64];
    __shared__ float sx[8][64];
    int tid = threadIdx.x, lane = tid & 31, wl = tid >> 5;
    for (int i = tid; i < 3 * 4096; i += 256) sW[i] = W_mlp[i];
    if (tid < 192) sb[tid] = b_mlp[tid];
    if (tid < 64) sWo[tid] = W_out[tid];
    __syncthreads();
    float wd = w_d[0], bd = b_d[0], bo = b_out[0];
    int g = blockIdx.x * 8 + wl;
    if (g >= g_total) return;

    int beg = goff[g], end = goff[g + 1];
    float s00 = 0.f, s01 = 0.f, s10 = 0.f, s11 = 0.f, sg = 0.f;
    for (int nn = beg; nn < end; nn++) {
        float gate = 1.0f / (1.0f + __expf(-(d_edge[nn] * wd + bd)));
        float2 hp = __half22float2(h16[(size_t)nn * 32 + lane]);
        s00 += hp.x; s01 += hp.y;
        s10 += gate * hp.x; s11 += gate * hp.y;
        sg += gate;
    }
    float iv = i_node[g];
    float hi0 = iv * W_i[2 * lane] + s10;
    float hi1 = iv * W_i[2 * lane + 1] + s11;
    sx[wl][2 * lane]     = s00 + sg * hi0;
    sx[wl][2 * lane + 1] = s01 + sg * hi1;
    __syncwarp();

    for (int l = 0; l < 3; l++) {
        float a0 = sb[l * 64 + 2 * lane];
        float a1 = sb[l * 64 + 2 * lane + 1];
        const float* Wl = sW + l * 4096;
        #pragma unroll 8
        for (int k = 0; k < 64; k++) {
            float xv = sx[wl][k];
            a0 += xv * Wl[k * 64 + 2 * lane];
            a1 += xv * Wl[k * 64 + 2 * lane + 1];
        }
        a0 = fmaxf(a0, 0.f);
        a1 = fmaxf(a1, 0.f);
        __syncwarp();
        sx[wl][2 * lane]     = a0;
        sx[wl][2 * lane + 1] = a1;
        __syncwarp();
    }
    float part = sx[wl][2 * lane] * sWo[2 * lane] + sx[wl][2 * lane + 1] * sWo[2 * lane + 1];
    #pragma unroll
    for (int d = 16; d; d >>= 1) part += __shfl_xor_sync(0xffffffffu, part, d);
    if (lane == 0) out[g] = part + bo;
}

// ---------------- launcher ----------------
extern "C" void kernel_launch(void* const* d_in, const int* in_sizes, int n_in,
                              void* d_out, int out_size) {
    const float* r_node  = (const float*)d_in[0];
    const float* i_node  = (const float*)d_in[1];
    const float* r_edge  = (const float*)d_in[2];
    const float* d_edge  = (const float*)d_in[3];
    const int*   r2r_src = (const int*)d_in[4];
    const int*   r2r_dst = (const int*)d_in[5];
    const int*   graph_id= (const int*)d_in[6];
    const float* W_r     = (const float*)d_in[7];
    const float* W_i     = (const float*)d_in[8];
    const float* W_e     = (const float*)d_in[9];
    const float* Wm      = (const float*)d_in[10];
    const float* a_s     = (const float*)d_in[11];
    const float* a_d     = (const float*)d_in[12];
    const float* a_e     = (const float*)d_in[13];
    const float* w_d     = (const float*)d_in[14];
    const float* b_d     = (const float*)d_in[15];
    const float* W_mlp   = (const float*)d_in[16];
    const float* b_mlp   = (const float*)d_in[17];
    const float* W_out   = (const float*)d_in[18];
    const float* b_out   = (const float*)d_in[19];
    float* out = (float*)d_out;

    const int nN = in_sizes[3];
    const int nE = in_sizes[4];
    const int nG = in_sizes[1];

    float *p_h, *p_hs, *p_hd;
    __half2 *p_h16, *p_agg16;
    uint4*   p_recsr;
    int *p_deg, *p_off, *p_cur, *p_srcs, *p_gcnt, *p_goff, *p_bsums;
    cudaGetSymbolAddress((void**)&p_h, g_h);
    cudaGetSymbolAddress((void**)&p_h16, g_h16);
    cudaGetSymbolAddress((void**)&p_agg16, g_agg16);
    cudaGetSymbolAddress((void**)&p_hs, g_hs);
    cudaGetSymbolAddress((void**)&p_hd, g_hd);
    cudaGetSymbolAddress((void**)&p_recsr, g_recsr);
    cudaGetSymbolAddress((void**)&p_deg, g_deg);
    cudaGetSymbolAddress((void**)&p_off, g_off);
    cudaGetSymbolAddress((void**)&p_cur, g_cur);
    cudaGetSymbolAddress((void**)&p_srcs, g_srcs);
    cudaGetSymbolAddress((void**)&p_gcnt, g_gcnt);
    cudaGetSymbolAddress((void**)&p_goff, g_goff);
    cudaGetSymbolAddress((void**)&p_bsums, g_bsums);

    int nbN = (nN + 1023) / 1024;
    int layer_blocks = (nN + NB - 1) / NB;

    // 0: zero, 1: hist, 2: scanN, 3: gemm (ncu window)
    zero_fused<<<(nN + 255) / 256, 256>>>(p_deg, p_cur, p_gcnt, nN, nG);
    hist_fused<<<(nE + 255) / 256, 256>>>(r2r_dst, graph_id, p_deg, p_gcnt, nE, nN);
    scan_block<<<nbN, 1024>>>(p_deg, p_off, p_bsums, nN);
    gemm64_t<false><<<592, 256>>>(r_node, nullptr, W_r, nullptr, p_h, p_h16,
                                  a_s, a_d, p_hs, p_hd, nN, 0);
    scan_sums_par<<<1, 128>>>(p_bsums, nbN);
    add_base<<<nbN, 1024>>>(p_off, p_bsums, nN);
    scan_small<<<1, 1024>>>(p_gcnt, p_goff, nG);
    scatter_recsr_kernel<<<(nE + 255) / 256, 256>>>(r2r_src, r2r_dst, r_edge,
                                                    p_off, p_cur, p_srcs, p_recsr, nE);

    // --- 4 attention conv layers ---
    for (int l = 0; l < LYR; l++) {
        layer_kernel<<<layer_blocks, 256>>>(p_off, p_srcs, p_recsr, W_e, a_e, l,
                                            p_hs, p_hd, p_h16, p_agg16, nN);
        const float* as_next = (l < LYR - 1) ? (a_s + (l + 1) * H) : nullptr;
        const float* ad_next = (l < LYR - 1) ? (a_d + (l + 1) * H) : nullptr;
        gemm64_t<true><<<592, 256>>>(nullptr, p_agg16, Wm + (size_t)l * H * H,
                                     p_h, p_h, p_h16,
                                     as_next, ad_next, p_hs, p_hd, nN, 1);
    }

    // --- fused pool + interaction + MLP ---
    poolmlp_kernel<<<(nG + 7) / 8, 256>>>(p_goff, d_edge, w_d, b_d, i_node, W_i,
                                          p_h16, W_mlp, b_mlp, W_out, b_out, out, nG);
}